// round 15
// baseline (speedup 1.0000x reference)
#include <cuda_runtime.h>
#include <cuda_fp16.h>

// Problem constants
#define Bn 2
#define Tn 2048
#define Cn 1024
#define Hn 16
#define Dn 64
#define BT (Bn * Tn)                       // 4096
#define YSIZE (BT * Cn)                    // 4194304
#define QKVSZ (Bn * Hn * Tn * Dn)          // 4194304

typedef unsigned short u16;
typedef unsigned int u32;

// f16 plane scratch (device globals -- no allocation allowed)
__device__ u16 g_xFH[YSIZE], g_xFL[YSIZE];   // x f16 hi/lo
__device__ u16 g_WqFH[Cn*Cn];                // weights f16 hi only
__device__ u16 g_WkFH[Cn*Cn];
__device__ u16 g_WvFH[Cn*Cn];
__device__ u16 g_WoFH[Cn*Cn];
__device__ u16 g_Qh[QKVSZ];                  // fp16 single plane [B,H,T,D]
__device__ u16 g_Kh[QKVSZ];
__device__ u16 g_Vh[QKVSZ];
__device__ u16 g_YFH[YSIZE], g_YFL[YSIZE];   // [B,T,C] f16 hi/lo
__device__ float g_Linv[Bn * Hn * Tn];

// ---------------------------------------------------------------------------
// helpers
// ---------------------------------------------------------------------------
__device__ __forceinline__ u32 sptr(const void* p) {
    return (u32)__cvta_generic_to_shared(p);
}
__device__ __forceinline__ void split1h(float x, u16& h, u16& l) {
    __half hb = __float2half(x);
    h = __half_as_ushort(hb);
    l = __half_as_ushort(__float2half(x - __half2float(hb)));
}
__device__ __forceinline__ void split_store4h(u16* H, u16* L, int idx, float4 v) {
    u16 h[4], l[4];
    split1h(v.x, h[0], l[0]); split1h(v.y, h[1], l[1]);
    split1h(v.z, h[2], l[2]); split1h(v.w, h[3], l[3]);
    *(uint2*)(H + idx) = make_uint2((u32)h[0] | ((u32)h[1] << 16),
                                    (u32)h[2] | ((u32)h[3] << 16));
    *(uint2*)(L + idx) = make_uint2((u32)l[0] | ((u32)l[1] << 16),
                                    (u32)l[2] | ((u32)l[3] << 16));
}
__device__ __forceinline__ void store4h_hi(u16* H, int idx, float4 v) {
    u16 h0 = __half_as_ushort(__float2half(v.x));
    u16 h1 = __half_as_ushort(__float2half(v.y));
    u16 h2 = __half_as_ushort(__float2half(v.z));
    u16 h3 = __half_as_ushort(__float2half(v.w));
    *(uint2*)(H + idx) = make_uint2((u32)h0 | ((u32)h1 << 16),
                                    (u32)h2 | ((u32)h3 << 16));
}
// fp16 mma
__device__ __forceinline__ void mma16h(float c[4], const u32 a[4], u32 b0, u32 b1) {
    asm volatile(
        "mma.sync.aligned.m16n8k16.row.col.f32.f16.f16.f32 "
        "{%0,%1,%2,%3}, {%4,%5,%6,%7}, {%8,%9}, {%0,%1,%2,%3};\n"
        : "+f"(c[0]), "+f"(c[1]), "+f"(c[2]), "+f"(c[3])
        : "r"(a[0]), "r"(a[1]), "r"(a[2]), "r"(a[3]), "r"(b0), "r"(b1));
}
__device__ __forceinline__ void ldsm4(u32 r[4], u32 addr) {
    asm volatile("ldmatrix.sync.aligned.m8n8.x4.shared.b16 {%0,%1,%2,%3}, [%4];"
        : "=r"(r[0]), "=r"(r[1]), "=r"(r[2]), "=r"(r[3]) : "r"(addr));
}
__device__ __forceinline__ void ldsm4t(u32 r[4], u32 addr) {
    asm volatile("ldmatrix.sync.aligned.m8n8.x4.trans.shared.b16 {%0,%1,%2,%3}, [%4];"
        : "=r"(r[0]), "=r"(r[1]), "=r"(r[2]), "=r"(r[3]) : "r"(addr));
}
__device__ __forceinline__ void cpa16(u32 sdst, const void* g) {
    asm volatile("cp.async.cg.shared.global [%0], [%1], 16;\n" :: "r"(sdst), "l"(g));
}
#define CP_COMMIT() asm volatile("cp.async.commit_group;\n")
#define CP_WAIT0()  asm volatile("cp.async.wait_group 0;\n")

// ---------------------------------------------------------------------------
// Fused prep: x -> f16 hi/lo planes; Wq,Wk,Wv,Wo -> f16 hi plane.
// ---------------------------------------------------------------------------
__global__ __launch_bounds__(256) void split_all_kernel(
    const float* __restrict__ x,  const float* __restrict__ wq,
    const float* __restrict__ wk, const float* __restrict__ wv,
    const float* __restrict__ wo)
{
    int i = (blockIdx.x * 256 + threadIdx.x) * 4;
    if (i < YSIZE) {
        split_store4h(g_xFH, g_xFL, i, *(const float4*)(x + i));
    } else {
        int k = i - YSIZE;
        int seg = k >> 20;
        int off = k & ((1 << 20) - 1);
        switch (seg) {
            case 0: store4h_hi(g_WqFH, off, *(const float4*)(wq + off)); break;
            case 1: store4h_hi(g_WkFH, off, *(const float4*)(wk + off)); break;
            case 2: store4h_hi(g_WvFH, off, *(const float4*)(wv + off)); break;
            default: store4h_hi(g_WoFH, off, *(const float4*)(wo + off)); break;
        }
    }
}

// ---------------------------------------------------------------------------
// GEMM mainloop (2-stage, proven R12 config): C(128x128) = (Ah+Al) @ Wh^T.
// 256 threads = 8 warps (wy 2 x wx 4), warp tile 64x32, k-chunk 32, dbuf.
// smem: [stage 2][plane 3: AH AL WH][128][40] = 61440 bytes, 2 CTAs/SM.
// ---------------------------------------------------------------------------
#define G2STR 40
#define G2PLANE (128 * G2STR)            // 5120 u16
#define G2STAGE (3 * G2PLANE)            // 15360 u16
#define GEMM2_SMEM (2 * G2STAGE * 2)     // 61440 bytes

__device__ __forceinline__ void gemm_mainloop(
    const u16* __restrict__ AH, const u16* __restrict__ AL,
    const u16* __restrict__ WH,
    int m0, int n0, float acc[4][4][4])
{
    extern __shared__ u16 gsm[];
    const int tid = threadIdx.x, lane = tid & 31, w = tid >> 5;
    const int wy = w >> 2, wx = w & 3;
    const u32 sbase = sptr(gsm);
    const u32 aoff = (lane & 15) * (G2STR * 2) + (lane >> 4) * 16;
    const u32 boff = ((lane & 7) + ((lane >> 4) << 3)) * (G2STR * 2) + ((lane >> 3) & 1) * 16;

    const u16* srcs[3] = {AH, AL, WH};
    const int rb3[3] = {m0, m0, n0};

    auto loadbuf = [&](int stg, int kc) {
        #pragma unroll
        for (int p = 0; p < 3; p++) {
            const u16* sp = srcs[p];
            #pragma unroll
            for (int j = 0; j < 2; j++) {
                int c = tid + 256 * j;
                int r = c >> 2, c16 = c & 3;
                u32 d = sbase + (stg * G2STAGE + p * G2PLANE + r * G2STR + c16 * 8) * 2;
                cpa16(d, sp + (size_t)(rb3[p] + r) * Cn + kc * 32 + c16 * 8);
            }
        }
    };

    loadbuf(0, 0); CP_COMMIT(); CP_WAIT0();
    __syncthreads();

    const int NC = Cn / 32;   // 32
    for (int kc = 0; kc < NC; kc++) {
        const int buf = kc & 1;
        if (kc + 1 < NC) { loadbuf(buf ^ 1, kc + 1); CP_COMMIT(); }

        const u32 ab  = sbase + (buf * G2STAGE + 0 * G2PLANE) * 2;
        const u32 alb = sbase + (buf * G2STAGE + 1 * G2PLANE) * 2;
        const u32 wb  = sbase + (buf * G2STAGE + 2 * G2PLANE) * 2;

        #pragma unroll
        for (int s = 0; s < 2; s++) {
            const u32 kb = s * 32;
            u32 ah[4][4], al[4][4];
            #pragma unroll
            for (int mt = 0; mt < 4; mt++) {
                const u32 rb = (wy * 64 + mt * 16) * (G2STR * 2) + kb + aoff;
                ldsm4(ah[mt], ab + rb);
                ldsm4(al[mt], alb + rb);
            }
            u32 bh[2][4];
            #pragma unroll
            for (int p = 0; p < 2; p++)
                ldsm4(bh[p], wb + (wx * 32 + p * 16) * (G2STR * 2) + kb + boff);
            #pragma unroll
            for (int nt = 0; nt < 4; nt++) {
                const u32 b0 = bh[nt >> 1][(nt & 1) * 2], b1 = bh[nt >> 1][(nt & 1) * 2 + 1];
                #pragma unroll
                for (int mt = 0; mt < 4; mt++) {
                    mma16h(acc[mt][nt], ah[mt], b0, b1);
                    mma16h(acc[mt][nt], al[mt], b0, b1);
                }
            }
        }
        if (kc + 1 < NC) { CP_WAIT0(); __syncthreads(); }
    }
}

// ---------------------------------------------------------------------------
// Fused QKV projection. All outputs stored as single fp16 plane [B,H,T,D].
// ---------------------------------------------------------------------------
__global__ __launch_bounds__(256, 2) void qkv_kernel(
    const float* __restrict__ bq, const float* __restrict__ bk,
    const float* __restrict__ bv)
{
    const int mode = blockIdx.z;
    const float* bias = mode == 0 ? bq : (mode == 1 ? bk : bv);
    const u16* W = mode == 0 ? g_WqFH : (mode == 1 ? g_WkFH : g_WvFH);
    u16* dst = mode == 0 ? g_Qh : (mode == 1 ? g_Kh : g_Vh);

    const int m0 = blockIdx.y * 128, n0 = blockIdx.x * 128;
    float acc[4][4][4] = {};
    gemm_mainloop(g_xFH, g_xFL, W, m0, n0, acc);

    const int tid = threadIdx.x;
    const int w = tid >> 5, lane = tid & 31;
    const int wy = w >> 2, wx = w & 3;
    const int grp = lane >> 2, tig = lane & 3;

    #pragma unroll
    for (int mt = 0; mt < 4; mt++) {
        #pragma unroll
        for (int half = 0; half < 2; half++) {
            const int m = m0 + wy * 64 + mt * 16 + grp + 8 * half;
            const int b = m >> 11;
            const int t = m & (Tn - 1);
            #pragma unroll
            for (int nt = 0; nt < 4; nt++) {
                const int n = n0 + wx * 32 + nt * 8 + 2 * tig;
                const int h = n >> 6, d = n & 63;
                float e0 = acc[mt][nt][half * 2 + 0] + bias[n];
                float e1 = acc[mt][nt][half * 2 + 1] + bias[n + 1];
                u16 q0 = __half_as_ushort(__float2half(e0));
                u16 q1 = __half_as_ushort(__float2half(e1));
                const size_t idx = ((size_t)(b * Hn + h) * Tn + t) * Dn + d;
                *(u32*)&dst[idx] = (u32)q0 | ((u32)q1 << 16);
            }
        }
    }
}

// ---------------------------------------------------------------------------
// Combined epilogue kernel: blocks [0,256) = output projection (tensor-bound),
// blocks [256, 256+8192) = att normalization (DRAM-bound). Heterogeneous CTAs
// co-reside on SMs -> memory traffic hides under GEMM compute.
// ---------------------------------------------------------------------------
__global__ __launch_bounds__(256, 2) void oproj_scale_kernel(
    const float* __restrict__ bo, float* __restrict__ out,
    float* __restrict__ att)
{
    if (blockIdx.x < 256) {
        // ---- oproj path ----
        const int m0 = (blockIdx.x >> 3) * 128, n0 = (blockIdx.x & 7) * 128;
        float acc[4][4][4] = {};
        gemm_mainloop(g_YFH, g_YFL, g_WoFH, m0, n0, acc);

        const int tid = threadIdx.x;
        const int w = tid >> 5, lane = tid & 31;
        const int wy = w >> 2, wx = w & 3;
        const int grp = lane >> 2, tig = lane & 3;

        #pragma unroll
        for (int mt = 0; mt < 4; mt++) {
            #pragma unroll
            for (int half = 0; half < 2; half++) {
                const int m = m0 + wy * 64 + mt * 16 + grp + 8 * half;
                #pragma unroll
                for (int nt = 0; nt < 4; nt++) {
                    const int n = n0 + wx * 32 + nt * 8 + 2 * tig;
                    float2 o = make_float2(acc[mt][nt][half * 2 + 0] + bo[n],
                                           acc[mt][nt][half * 2 + 1] + bo[n + 1]);
                    *(float2*)&out[(size_t)m * Cn + n] = o;
                }
            }
        }
    } else {
        // ---- att normalization path: 8 rows per block, one warp per row ----
        const int tid = threadIdx.x;
        const int row = (blockIdx.x - 256) * 8 + (tid >> 5);
        const int lane = tid & 31;
        const int t = row & (Tn - 1);
        const float s = g_Linv[row];
        float4* p4 = (float4*)(att + (size_t)row * Tn);
        const int n4 = (t >> 2) + 1;
        for (int i = lane; i < n4; i += 32) {
            float4 v = p4[i];
            v.x *= s; v.y *= s; v.z *= s; v.w *= s;
            p4[i] = v;
        }
    }
}

// ---------------------------------------------------------------------------
// Causal attention. S: f16 x1 (Q/K single plane). PV: f16 x1 (P single, V single).
// smem u16: Q[128][72] | K[128][72] | V[2buf][128][72] | PH[128][136] | rowsum
// ---------------------------------------------------------------------------
#define GSTR 72
#define GS (128 * GSTR)
#define PSTR 136
#define PS (128 * PSTR)
#define AQ  0
#define AK  GS
#define AVB (2 * GS)                 // 2 bufs: 2GS..4GS
#define APH (4 * GS)                 // 36864
#define ARS (APH + PS)               // 54272
#define ATTN_SMEM (ARS * 2 + 512)    // 109056 bytes

__global__ __launch_bounds__(512) void attn_kernel(float* __restrict__ att)
{
    extern __shared__ u16 smu[];
    float* rowsum = (float*)(smu + ARS);

    const u32 sbase = sptr(smu);
    const u32 sQ  = sbase;
    const u32 sK  = sbase + AK * 2;
    const u32 sPH = sbase + APH * 2;

    const int tid = threadIdx.x;
    const int w = tid >> 5, lane = tid & 31;
    const int wy = w >> 2, wx = w & 3;
    const int grp = lane >> 2, tig = lane & 3;

    const int qt = gridDim.x - 1 - blockIdx.x;
    const int h = blockIdx.y, b = blockIdx.z;
    const int bh = b * Hn + h;
    const int q0 = qt * 128;
    const size_t qb = (size_t)bh * Tn * Dn;
    float* attp = att + (size_t)bh * Tn * Tn + (size_t)q0 * Tn;

    const u32 aoff = (lane & 15) * (GSTR * 2) + (lane >> 4) * 16;
    const u32 boff = ((lane & 7) + ((lane >> 4) << 3)) * (GSTR * 2) + ((lane >> 3) & 1) * 16;
    const u32 poff = (lane & 15) * (PSTR * 2) + (lane >> 4) * 16;

    auto loadQ = [&]() {
        #pragma unroll
        for (int j = 0; j < 2; j++) {
            int c = tid + 512 * j;
            int r = c >> 3, col = (c & 7) * 8;
            cpa16(sbase + (AQ + r * GSTR + col) * 2, g_Qh + qb + (size_t)(q0 + r) * Dn + col);
        }
    };
    auto loadK = [&](int kt) {
        #pragma unroll
        for (int j = 0; j < 2; j++) {
            int c = tid + 512 * j;
            int r = c >> 3, col = (c & 7) * 8;
            cpa16(sbase + (AK + r * GSTR + col) * 2, g_Kh + qb + (size_t)(kt * 128 + r) * Dn + col);
        }
    };
    auto loadV = [&](int kt, int vb) {
        #pragma unroll
        for (int j = 0; j < 2; j++) {
            int c = tid + 512 * j;
            int r = c >> 3, col = (c & 7) * 8;
            cpa16(sbase + ((AVB + vb * GS) + r * GSTR + col) * 2,
                  g_Vh + qb + (size_t)(kt * 128 + r) * Dn + col);
        }
    };

    if (tid < 128) rowsum[tid] = 0.f;
    loadQ();
    loadK(0);
    loadV(0, 0);
    CP_COMMIT();
    CP_WAIT0();
    __syncthreads();

    float accy[2][2][4] = {};
    float lpart[2][2] = {};
    const int qbl = wy * 32;

    for (int kt = 0; kt <= qt; kt++) {
        const int k0 = kt * 128;
        const int vb = kt & 1;
        const int ktn = (kt + 1 <= qt) ? kt + 1 : qt;

        loadV(ktn, vb ^ 1);
        CP_COMMIT();

        // ---- S = Q K^T (fp16 x1) ----
        float sfrag[2][4][4] = {};
        #pragma unroll
        for (int ds = 0; ds < 4; ds++) {
            const u32 kb = ds * 32;
            u32 ah[2][4];
            #pragma unroll
            for (int mt = 0; mt < 2; mt++)
                ldsm4(ah[mt], sQ + (qbl + mt * 16) * (GSTR * 2) + kb + aoff);
            u32 kh[2][4];
            #pragma unroll
            for (int p = 0; p < 2; p++)
                ldsm4(kh[p], sK + (wx * 32 + p * 16) * (GSTR * 2) + kb + boff);
            #pragma unroll
            for (int nt = 0; nt < 4; nt++) {
                const u32 b0 = kh[nt >> 1][(nt & 1) * 2], b1 = kh[nt >> 1][(nt & 1) * 2 + 1];
                #pragma unroll
                for (int mt = 0; mt < 2; mt++)
                    mma16h(sfrag[mt][nt], ah[mt], b0, b1);
            }
        }

        // ---- exp + mask; write att gmem (unnormalized f32) + P f16 plane ----
        #pragma unroll
        for (int mt = 0; mt < 2; mt++) {
            #pragma unroll
            for (int half = 0; half < 2; half++) {
                const int ql = qbl + mt * 16 + grp + 8 * half;
                const int qg = q0 + ql;
                #pragma unroll
                for (int nt = 0; nt < 4; nt++) {
                    const int klc = wx * 32 + nt * 8 + 2 * tig;
                    float e0 = (k0 + klc     <= qg) ? __expf(sfrag[mt][nt][half * 2 + 0] * 0.125f) : 0.f;
                    float e1 = (k0 + klc + 1 <= qg) ? __expf(sfrag[mt][nt][half * 2 + 1] * 0.125f) : 0.f;
                    lpart[mt][half] += e0 + e1;
                    *(float2*)(attp + (size_t)ql * Tn + k0 + klc) = make_float2(e0, e1);
                    u16 h0 = __half_as_ushort(__float2half(e0));
                    u16 h1 = __half_as_ushort(__float2half(e1));
                    *(u32*)&smu[APH + ql * PSTR + klc] = (u32)h0 | ((u32)h1 << 16);
                }
            }
        }
        __syncthreads();

        loadK(ktn);
        CP_COMMIT();

        // ---- y += P V (f16 x1), V via ldmatrix.trans ----
        const u32 sV = sbase + (AVB + vb * GS) * 2;
        #pragma unroll
        for (int ks = 0; ks < 8; ks++) {
            u32 ph[2][4];
            #pragma unroll
            for (int mt = 0; mt < 2; mt++)
                ldsm4(ph[mt], sPH + (qbl + mt * 16) * (PSTR * 2) + ks * 32 + poff);
            u32 vh[4];
            ldsm4t(vh, sV + (ks * 16) * (GSTR * 2) + wx * 32 + aoff);
            #pragma unroll
            for (int ntv = 0; ntv < 2; ntv++) {
                const u32 b0 = vh[2 * ntv], b1 = vh[2 * ntv + 1];
                #pragma unroll
                for (int mt = 0; mt < 2; mt++)
                    mma16h(accy[mt][ntv], ph[mt], b0, b1);
            }
        }

        CP_WAIT0();
        __syncthreads();
    }

    #pragma unroll
    for (int mt = 0; mt < 2; mt++) {
        #pragma unroll
        for (int half = 0; half < 2; half++) {
            float v = lpart[mt][half];
            v += __shfl_xor_sync(0xffffffffu, v, 1);
            v += __shfl_xor_sync(0xffffffffu, v, 2);
            if (tig == 0) atomicAdd(&rowsum[qbl + mt * 16 + grp + 8 * half], v);
        }
    }
    __syncthreads();
    if (tid < 128) g_Linv[(size_t)bh * Tn + q0 + tid] = 1.0f / rowsum[tid];

    // ---- write y (normalized) as f16 hi/lo planes ----
    #pragma unroll
    for (int mt = 0; mt < 2; mt++) {
        #pragma unroll
        for (int half = 0; half < 2; half++) {
            const int ql = qbl + mt * 16 + grp + 8 * half;
            const float li = 1.0f / rowsum[ql];
            const int tg = q0 + ql;
            #pragma unroll
            for (int ntv = 0; ntv < 2; ntv++) {
                const int d = wx * 16 + ntv * 8 + 2 * tig;
                float y0 = accy[mt][ntv][half * 2 + 0] * li;
                float y1 = accy[mt][ntv][half * 2 + 1] * li;
                u16 h0, l0, h1, l1;
                split1h(y0, h0, l0); split1h(y1, h1, l1);
                const size_t idx = (size_t)(b * Tn + tg) * Cn + h * Dn + d;
                *(u32*)&g_YFH[idx] = (u32)h0 | ((u32)h1 << 16);
                *(u32*)&g_YFL[idx] = (u32)l0 | ((u32)l1 << 16);
            }
        }
    }

    // ---- zero strictly-upper att region ----
    const int zc0 = (qt + 1) * 128;
    if (zc0 < Tn) {
        const int nz4 = (Tn - zc0) >> 2;
        for (int idx = tid; idx < 128 * nz4; idx += 512) {
            int r = idx / nz4, c = (idx - r * nz4) * 4;
            *(float4*)(attp + (size_t)r * Tn + zc0 + c) = make_float4(0.f, 0.f, 0.f, 0.f);
        }
    }
}

// ---------------------------------------------------------------------------
extern "C" void kernel_launch(void* const* d_in, const int* in_sizes, int n_in,
                              void* d_out, int out_size)
{
    const float* x  = (const float*)d_in[0];
    const float* Wq = (const float*)d_in[1];
    const float* bq = (const float*)d_in[2];
    const float* Wk = (const float*)d_in[3];
    const float* bk = (const float*)d_in[4];
    const float* Wv = (const float*)d_in[5];
    const float* bv = (const float*)d_in[6];
    const float* Wo = (const float*)d_in[7];
    const float* bo = (const float*)d_in[8];
    float* out = (float*)d_out;
    float* attOut = out + YSIZE;

    static int configured = 0;
    if (!configured) {
        cudaFuncSetAttribute(qkv_kernel,  cudaFuncAttributeMaxDynamicSharedMemorySize, GEMM2_SMEM);
        cudaFuncSetAttribute(oproj_scale_kernel, cudaFuncAttributeMaxDynamicSharedMemorySize, GEMM2_SMEM);
        cudaFuncSetAttribute(attn_kernel, cudaFuncAttributeMaxDynamicSharedMemorySize, ATTN_SMEM);
        configured = 1;
    }

    split_all_kernel<<<(YSIZE + 4 * Cn * Cn) / 1024, 256>>>(x, Wq, Wk, Wv, Wo);

    qkv_kernel<<<dim3(Cn / 128, BT / 128, 3), 256, GEMM2_SMEM>>>(bq, bk, bv);
    attn_kernel<<<dim3(Tn / 128, Hn, Bn), 512, ATTN_SMEM>>>(attOut);
    oproj_scale_kernel<<<256 + (Bn * Hn * Tn) / 8, 256, GEMM2_SMEM>>>(bo, out, attOut);
}

// round 16
// speedup vs baseline: 1.0963x; 1.0963x over previous
#include <cuda_runtime.h>
#include <cuda_fp16.h>

// Problem constants
#define Bn 2
#define Tn 2048
#define Cn 1024
#define Hn 16
#define Dn 64
#define BT (Bn * Tn)                       // 4096
#define YSIZE (BT * Cn)                    // 4194304
#define QKVSZ (Bn * Hn * Tn * Dn)          // 4194304

typedef unsigned short u16;
typedef unsigned int u32;

// f16 plane scratch (device globals -- no allocation allowed)
__device__ u16 g_xFH[YSIZE], g_xFL[YSIZE];   // x f16 hi/lo
__device__ u16 g_WqFH[Cn*Cn];                // weights f16 hi only
__device__ u16 g_WkFH[Cn*Cn];
__device__ u16 g_WvFH[Cn*Cn];
__device__ u16 g_WoFH[Cn*Cn];
__device__ u16 g_Qh[QKVSZ];                  // fp16 single plane [B,H,T,D], PRE-SCALED by 0.125*log2(e)
__device__ u16 g_Kh[QKVSZ];
__device__ u16 g_Vh[QKVSZ];
__device__ u16 g_YFH[YSIZE], g_YFL[YSIZE];   // [B,T,C] f16 hi/lo
__device__ float g_Linv[Bn * Hn * Tn];

// ---------------------------------------------------------------------------
// helpers
// ---------------------------------------------------------------------------
__device__ __forceinline__ u32 sptr(const void* p) {
    return (u32)__cvta_generic_to_shared(p);
}
__device__ __forceinline__ void split1h(float x, u16& h, u16& l) {
    __half hb = __float2half(x);
    h = __half_as_ushort(hb);
    l = __half_as_ushort(__float2half(x - __half2float(hb)));
}
__device__ __forceinline__ void split_store4h(u16* H, u16* L, int idx, float4 v) {
    u16 h[4], l[4];
    split1h(v.x, h[0], l[0]); split1h(v.y, h[1], l[1]);
    split1h(v.z, h[2], l[2]); split1h(v.w, h[3], l[3]);
    *(uint2*)(H + idx) = make_uint2((u32)h[0] | ((u32)h[1] << 16),
                                    (u32)h[2] | ((u32)h[3] << 16));
    *(uint2*)(L + idx) = make_uint2((u32)l[0] | ((u32)l[1] << 16),
                                    (u32)l[2] | ((u32)l[3] << 16));
}
__device__ __forceinline__ void store4h_hi(u16* H, int idx, float4 v) {
    u16 h0 = __half_as_ushort(__float2half(v.x));
    u16 h1 = __half_as_ushort(__float2half(v.y));
    u16 h2 = __half_as_ushort(__float2half(v.z));
    u16 h3 = __half_as_ushort(__float2half(v.w));
    *(uint2*)(H + idx) = make_uint2((u32)h0 | ((u32)h1 << 16),
                                    (u32)h2 | ((u32)h3 << 16));
}
// fp16 mma
__device__ __forceinline__ void mma16h(float c[4], const u32 a[4], u32 b0, u32 b1) {
    asm volatile(
        "mma.sync.aligned.m16n8k16.row.col.f32.f16.f16.f32 "
        "{%0,%1,%2,%3}, {%4,%5,%6,%7}, {%8,%9}, {%0,%1,%2,%3};\n"
        : "+f"(c[0]), "+f"(c[1]), "+f"(c[2]), "+f"(c[3])
        : "r"(a[0]), "r"(a[1]), "r"(a[2]), "r"(a[3]), "r"(b0), "r"(b1));
}
__device__ __forceinline__ void ldsm4(u32 r[4], u32 addr) {
    asm volatile("ldmatrix.sync.aligned.m8n8.x4.shared.b16 {%0,%1,%2,%3}, [%4];"
        : "=r"(r[0]), "=r"(r[1]), "=r"(r[2]), "=r"(r[3]) : "r"(addr));
}
__device__ __forceinline__ void ldsm4t(u32 r[4], u32 addr) {
    asm volatile("ldmatrix.sync.aligned.m8n8.x4.trans.shared.b16 {%0,%1,%2,%3}, [%4];"
        : "=r"(r[0]), "=r"(r[1]), "=r"(r[2]), "=r"(r[3]) : "r"(addr));
}
__device__ __forceinline__ void cpa16(u32 sdst, const void* g) {
    asm volatile("cp.async.cg.shared.global [%0], [%1], 16;\n" :: "r"(sdst), "l"(g));
}
#define CP_COMMIT() asm volatile("cp.async.commit_group;\n")
#define CP_WAIT0()  asm volatile("cp.async.wait_group 0;\n")

// ---------------------------------------------------------------------------
// Fused prep: x -> f16 hi/lo planes; Wq,Wk,Wv,Wo -> f16 hi plane.
// ---------------------------------------------------------------------------
__global__ __launch_bounds__(256) void split_all_kernel(
    const float* __restrict__ x,  const float* __restrict__ wq,
    const float* __restrict__ wk, const float* __restrict__ wv,
    const float* __restrict__ wo)
{
    int i = (blockIdx.x * 256 + threadIdx.x) * 4;
    if (i < YSIZE) {
        split_store4h(g_xFH, g_xFL, i, *(const float4*)(x + i));
    } else {
        int k = i - YSIZE;
        int seg = k >> 20;
        int off = k & ((1 << 20) - 1);
        switch (seg) {
            case 0: store4h_hi(g_WqFH, off, *(const float4*)(wq + off)); break;
            case 1: store4h_hi(g_WkFH, off, *(const float4*)(wk + off)); break;
            case 2: store4h_hi(g_WvFH, off, *(const float4*)(wv + off)); break;
            default: store4h_hi(g_WoFH, off, *(const float4*)(wo + off)); break;
        }
    }
}

// ---------------------------------------------------------------------------
// GEMM mainloop (2-stage, proven R12 config): C(128x128) = (Ah+Al) @ Wh^T.
// 256 threads = 8 warps (wy 2 x wx 4), warp tile 64x32, k-chunk 32, dbuf.
// smem: [stage 2][plane 3: AH AL WH][128][40] = 61440 bytes, 2 CTAs/SM.
// ---------------------------------------------------------------------------
#define G2STR 40
#define G2PLANE (128 * G2STR)            // 5120 u16
#define G2STAGE (3 * G2PLANE)            // 15360 u16
#define GEMM2_SMEM (2 * G2STAGE * 2)     // 61440 bytes

__device__ __forceinline__ void gemm_mainloop(
    const u16* __restrict__ AH, const u16* __restrict__ AL,
    const u16* __restrict__ WH,
    int m0, int n0, float acc[4][4][4])
{
    extern __shared__ u16 gsm[];
    const int tid = threadIdx.x, lane = tid & 31, w = tid >> 5;
    const int wy = w >> 2, wx = w & 3;
    const u32 sbase = sptr(gsm);
    const u32 aoff = (lane & 15) * (G2STR * 2) + (lane >> 4) * 16;
    const u32 boff = ((lane & 7) + ((lane >> 4) << 3)) * (G2STR * 2) + ((lane >> 3) & 1) * 16;

    const u16* srcs[3] = {AH, AL, WH};
    const int rb3[3] = {m0, m0, n0};

    auto loadbuf = [&](int stg, int kc) {
        #pragma unroll
        for (int p = 0; p < 3; p++) {
            const u16* sp = srcs[p];
            #pragma unroll
            for (int j = 0; j < 2; j++) {
                int c = tid + 256 * j;
                int r = c >> 2, c16 = c & 3;
                u32 d = sbase + (stg * G2STAGE + p * G2PLANE + r * G2STR + c16 * 8) * 2;
                cpa16(d, sp + (size_t)(rb3[p] + r) * Cn + kc * 32 + c16 * 8);
            }
        }
    };

    loadbuf(0, 0); CP_COMMIT(); CP_WAIT0();
    __syncthreads();

    const int NC = Cn / 32;   // 32
    for (int kc = 0; kc < NC; kc++) {
        const int buf = kc & 1;
        if (kc + 1 < NC) { loadbuf(buf ^ 1, kc + 1); CP_COMMIT(); }

        const u32 ab  = sbase + (buf * G2STAGE + 0 * G2PLANE) * 2;
        const u32 alb = sbase + (buf * G2STAGE + 1 * G2PLANE) * 2;
        const u32 wb  = sbase + (buf * G2STAGE + 2 * G2PLANE) * 2;

        #pragma unroll
        for (int s = 0; s < 2; s++) {
            const u32 kb = s * 32;
            u32 ah[4][4], al[4][4];
            #pragma unroll
            for (int mt = 0; mt < 4; mt++) {
                const u32 rb = (wy * 64 + mt * 16) * (G2STR * 2) + kb + aoff;
                ldsm4(ah[mt], ab + rb);
                ldsm4(al[mt], alb + rb);
            }
            u32 bh[2][4];
            #pragma unroll
            for (int p = 0; p < 2; p++)
                ldsm4(bh[p], wb + (wx * 32 + p * 16) * (G2STR * 2) + kb + boff);
            #pragma unroll
            for (int nt = 0; nt < 4; nt++) {
                const u32 b0 = bh[nt >> 1][(nt & 1) * 2], b1 = bh[nt >> 1][(nt & 1) * 2 + 1];
                #pragma unroll
                for (int mt = 0; mt < 4; mt++) {
                    mma16h(acc[mt][nt], ah[mt], b0, b1);
                    mma16h(acc[mt][nt], al[mt], b0, b1);
                }
            }
        }
        if (kc + 1 < NC) { CP_WAIT0(); __syncthreads(); }
    }
}

// ---------------------------------------------------------------------------
// Fused QKV projection. Outputs single fp16 plane [B,H,T,D].
// Q is PRE-SCALED by 0.125*log2(e) so S = Q K^T is directly the exp2 argument.
// ---------------------------------------------------------------------------
__global__ __launch_bounds__(256, 2) void qkv_kernel(
    const float* __restrict__ bq, const float* __restrict__ bk,
    const float* __restrict__ bv)
{
    const int mode = blockIdx.z;
    const float* bias = mode == 0 ? bq : (mode == 1 ? bk : bv);
    const u16* W = mode == 0 ? g_WqFH : (mode == 1 ? g_WkFH : g_WvFH);
    u16* dst = mode == 0 ? g_Qh : (mode == 1 ? g_Kh : g_Vh);
    const float osc = (mode == 0) ? 0.18033688f : 1.0f;   // 0.125 * log2(e)

    const int m0 = blockIdx.y * 128, n0 = blockIdx.x * 128;
    float acc[4][4][4] = {};
    gemm_mainloop(g_xFH, g_xFL, W, m0, n0, acc);

    const int tid = threadIdx.x;
    const int w = tid >> 5, lane = tid & 31;
    const int wy = w >> 2, wx = w & 3;
    const int grp = lane >> 2, tig = lane & 3;

    #pragma unroll
    for (int mt = 0; mt < 4; mt++) {
        #pragma unroll
        for (int half = 0; half < 2; half++) {
            const int m = m0 + wy * 64 + mt * 16 + grp + 8 * half;
            const int b = m >> 11;
            const int t = m & (Tn - 1);
            #pragma unroll
            for (int nt = 0; nt < 4; nt++) {
                const int n = n0 + wx * 32 + nt * 8 + 2 * tig;
                const int h = n >> 6, d = n & 63;
                float e0 = (acc[mt][nt][half * 2 + 0] + bias[n]) * osc;
                float e1 = (acc[mt][nt][half * 2 + 1] + bias[n + 1]) * osc;
                u16 q0 = __half_as_ushort(__float2half(e0));
                u16 q1 = __half_as_ushort(__float2half(e1));
                const size_t idx = ((size_t)(b * Hn + h) * Tn + t) * Dn + d;
                *(u32*)&dst[idx] = (u32)q0 | ((u32)q1 << 16);
            }
        }
    }
}

// ---------------------------------------------------------------------------
// Output projection: out = (Yh+Yl) @ WoH^T + bo.
// ---------------------------------------------------------------------------
__global__ __launch_bounds__(256, 2) void oproj_kernel(
    const float* __restrict__ bo, float* __restrict__ out)
{
    const int m0 = blockIdx.y * 128, n0 = blockIdx.x * 128;
    float acc[4][4][4] = {};
    gemm_mainloop(g_YFH, g_YFL, g_WoFH, m0, n0, acc);

    const int tid = threadIdx.x;
    const int w = tid >> 5, lane = tid & 31;
    const int wy = w >> 2, wx = w & 3;
    const int grp = lane >> 2, tig = lane & 3;

    #pragma unroll
    for (int mt = 0; mt < 4; mt++) {
        #pragma unroll
        for (int half = 0; half < 2; half++) {
            const int m = m0 + wy * 64 + mt * 16 + grp + 8 * half;
            #pragma unroll
            for (int nt = 0; nt < 4; nt++) {
                const int n = n0 + wx * 32 + nt * 8 + 2 * tig;
                float2 o = make_float2(acc[mt][nt][half * 2 + 0] + bo[n],
                                       acc[mt][nt][half * 2 + 1] + bo[n + 1]);
                *(float2*)&out[(size_t)m * Cn + n] = o;
            }
        }
    }
}

// ---------------------------------------------------------------------------
// Causal attention. S = Q K^T is in log2 domain; e = 2^S via ex2.approx.f16x2
// (one MUFU per TWO elements). P plane gets the raw half2 bits. Diagonal tile
// applies the causal mask; off-diagonal tiles skip masking entirely.
// smem u16: Q[128][72] | K[128][72] | V[2buf][128][72] | PH[128][136] | rowsum
// ---------------------------------------------------------------------------
#define GSTR 72
#define GS (128 * GSTR)
#define PSTR 136
#define PS (128 * PSTR)
#define AQ  0
#define AK  GS
#define AVB (2 * GS)                 // 2 bufs: 2GS..4GS
#define APH (4 * GS)                 // 36864
#define ARS (APH + PS)               // 54272
#define ATTN_SMEM (ARS * 2 + 512)    // 109056 bytes

__global__ __launch_bounds__(512) void attn_kernel(float* __restrict__ att)
{
    extern __shared__ u16 smu[];
    float* rowsum = (float*)(smu + ARS);

    const u32 sbase = sptr(smu);
    const u32 sQ  = sbase;
    const u32 sK  = sbase + AK * 2;
    const u32 sPH = sbase + APH * 2;

    const int tid = threadIdx.x;
    const int w = tid >> 5, lane = tid & 31;
    const int wy = w >> 2, wx = w & 3;
    const int grp = lane >> 2, tig = lane & 3;

    const int qt = gridDim.x - 1 - blockIdx.x;
    const int h = blockIdx.y, b = blockIdx.z;
    const int bh = b * Hn + h;
    const int q0 = qt * 128;
    const size_t qb = (size_t)bh * Tn * Dn;
    float* attp = att + (size_t)bh * Tn * Tn + (size_t)q0 * Tn;

    const u32 aoff = (lane & 15) * (GSTR * 2) + (lane >> 4) * 16;
    const u32 boff = ((lane & 7) + ((lane >> 4) << 3)) * (GSTR * 2) + ((lane >> 3) & 1) * 16;
    const u32 poff = (lane & 15) * (PSTR * 2) + (lane >> 4) * 16;

    auto loadQ = [&]() {
        #pragma unroll
        for (int j = 0; j < 2; j++) {
            int c = tid + 512 * j;
            int r = c >> 3, col = (c & 7) * 8;
            cpa16(sbase + (AQ + r * GSTR + col) * 2, g_Qh + qb + (size_t)(q0 + r) * Dn + col);
        }
    };
    auto loadK = [&](int kt) {
        #pragma unroll
        for (int j = 0; j < 2; j++) {
            int c = tid + 512 * j;
            int r = c >> 3, col = (c & 7) * 8;
            cpa16(sbase + (AK + r * GSTR + col) * 2, g_Kh + qb + (size_t)(kt * 128 + r) * Dn + col);
        }
    };
    auto loadV = [&](int kt, int vb) {
        #pragma unroll
        for (int j = 0; j < 2; j++) {
            int c = tid + 512 * j;
            int r = c >> 3, col = (c & 7) * 8;
            cpa16(sbase + ((AVB + vb * GS) + r * GSTR + col) * 2,
                  g_Vh + qb + (size_t)(kt * 128 + r) * Dn + col);
        }
    };

    if (tid < 128) rowsum[tid] = 0.f;
    loadQ();
    loadK(0);
    loadV(0, 0);
    CP_COMMIT();
    CP_WAIT0();
    __syncthreads();

    float accy[2][2][4] = {};
    float lpart[2][2] = {};
    const int qbl = wy * 32;

    for (int kt = 0; kt <= qt; kt++) {
        const int k0 = kt * 128;
        const int vb = kt & 1;
        const int ktn = (kt + 1 <= qt) ? kt + 1 : qt;

        loadV(ktn, vb ^ 1);
        CP_COMMIT();

        // ---- S = Q K^T (fp16 x1), result in log2 domain ----
        float sfrag[2][4][4] = {};
        #pragma unroll
        for (int ds = 0; ds < 4; ds++) {
            const u32 kb = ds * 32;
            u32 ah[2][4];
            #pragma unroll
            for (int mt = 0; mt < 2; mt++)
                ldsm4(ah[mt], sQ + (qbl + mt * 16) * (GSTR * 2) + kb + aoff);
            u32 kh[2][4];
            #pragma unroll
            for (int p = 0; p < 2; p++)
                ldsm4(kh[p], sK + (wx * 32 + p * 16) * (GSTR * 2) + kb + boff);
            #pragma unroll
            for (int nt = 0; nt < 4; nt++) {
                const u32 b0 = kh[nt >> 1][(nt & 1) * 2], b1 = kh[nt >> 1][(nt & 1) * 2 + 1];
                #pragma unroll
                for (int mt = 0; mt < 2; mt++)
                    mma16h(sfrag[mt][nt], ah[mt], b0, b1);
            }
        }

        // ---- e = 2^S via f16x2 MUFU; att gmem (f32) + P f16 plane ----
        if (kt < qt) {
            // no masking needed
            #pragma unroll
            for (int mt = 0; mt < 2; mt++) {
                #pragma unroll
                for (int half = 0; half < 2; half++) {
                    const int ql = qbl + mt * 16 + grp + 8 * half;
                    #pragma unroll
                    for (int nt = 0; nt < 4; nt++) {
                        const int klc = wx * 32 + nt * 8 + 2 * tig;
                        __half2 hs = __floats2half2_rn(sfrag[mt][nt][half * 2 + 0],
                                                       sfrag[mt][nt][half * 2 + 1]);
                        __half2 he = h2exp2(hs);
                        float2 ef = __half22float2(he);
                        lpart[mt][half] += ef.x + ef.y;
                        *(float2*)(attp + (size_t)ql * Tn + k0 + klc) = ef;
                        *(u32*)&smu[APH + ql * PSTR + klc] = *(u32*)&he;
                    }
                }
            }
        } else {
            // diagonal tile: apply causal mask
            #pragma unroll
            for (int mt = 0; mt < 2; mt++) {
                #pragma unroll
                for (int half = 0; half < 2; half++) {
                    const int ql = qbl + mt * 16 + grp + 8 * half;
                    const int qg = q0 + ql;
                    #pragma unroll
                    for (int nt = 0; nt < 4; nt++) {
                        const int klc = wx * 32 + nt * 8 + 2 * tig;
                        __half2 hs = __floats2half2_rn(sfrag[mt][nt][half * 2 + 0],
                                                       sfrag[mt][nt][half * 2 + 1]);
                        __half2 he = h2exp2(hs);
                        float2 ef = __half22float2(he);
                        if (k0 + klc     > qg) ef.x = 0.f;
                        if (k0 + klc + 1 > qg) ef.y = 0.f;
                        __half2 hm = __floats2half2_rn(ef.x, ef.y);
                        lpart[mt][half] += ef.x + ef.y;
                        *(float2*)(attp + (size_t)ql * Tn + k0 + klc) = ef;
                        *(u32*)&smu[APH + ql * PSTR + klc] = *(u32*)&hm;
                    }
                }
            }
        }
        __syncthreads();

        loadK(ktn);
        CP_COMMIT();

        // ---- y += P V (f16 x1), V via ldmatrix.trans ----
        const u32 sV = sbase + (AVB + vb * GS) * 2;
        #pragma unroll
        for (int ks = 0; ks < 8; ks++) {
            u32 ph[2][4];
            #pragma unroll
            for (int mt = 0; mt < 2; mt++)
                ldsm4(ph[mt], sPH + (qbl + mt * 16) * (PSTR * 2) + ks * 32 + poff);
            u32 vh[4];
            ldsm4t(vh, sV + (ks * 16) * (GSTR * 2) + wx * 32 + aoff);
            #pragma unroll
            for (int ntv = 0; ntv < 2; ntv++) {
                const u32 b0 = vh[2 * ntv], b1 = vh[2 * ntv + 1];
                #pragma unroll
                for (int mt = 0; mt < 2; mt++)
                    mma16h(accy[mt][ntv], ph[mt], b0, b1);
            }
        }

        CP_WAIT0();
        __syncthreads();
    }

    #pragma unroll
    for (int mt = 0; mt < 2; mt++) {
        #pragma unroll
        for (int half = 0; half < 2; half++) {
            float v = lpart[mt][half];
            v += __shfl_xor_sync(0xffffffffu, v, 1);
            v += __shfl_xor_sync(0xffffffffu, v, 2);
            if (tig == 0) atomicAdd(&rowsum[qbl + mt * 16 + grp + 8 * half], v);
        }
    }
    __syncthreads();
    if (tid < 128) g_Linv[(size_t)bh * Tn + q0 + tid] = 1.0f / rowsum[tid];

    // ---- write y (normalized) as f16 hi/lo planes ----
    #pragma unroll
    for (int mt = 0; mt < 2; mt++) {
        #pragma unroll
        for (int half = 0; half < 2; half++) {
            const int ql = qbl + mt * 16 + grp + 8 * half;
            const float li = 1.0f / rowsum[ql];
            const int tg = q0 + ql;
            #pragma unroll
            for (int ntv = 0; ntv < 2; ntv++) {
                const int d = wx * 16 + ntv * 8 + 2 * tig;
                float y0 = accy[mt][ntv][half * 2 + 0] * li;
                float y1 = accy[mt][ntv][half * 2 + 1] * li;
                u16 h0, l0, h1, l1;
                split1h(y0, h0, l0); split1h(y1, h1, l1);
                const size_t idx = (size_t)(b * Tn + tg) * Cn + h * Dn + d;
                *(u32*)&g_YFH[idx] = (u32)h0 | ((u32)h1 << 16);
                *(u32*)&g_YFL[idx] = (u32)l0 | ((u32)l1 << 16);
            }
        }
    }

    // ---- zero strictly-upper att region ----
    const int zc0 = (qt + 1) * 128;
    if (zc0 < Tn) {
        const int nz4 = (Tn - zc0) >> 2;
        for (int idx = tid; idx < 128 * nz4; idx += 512) {
            int r = idx / nz4, c = (idx - r * nz4) * 4;
            *(float4*)(attp + (size_t)r * Tn + zc0 + c) = make_float4(0.f, 0.f, 0.f, 0.f);
        }
    }
}

// ---------------------------------------------------------------------------
// Normalize att: causal region *= 1/l (upper zeroed by attn_kernel).
// ---------------------------------------------------------------------------
__global__ __launch_bounds__(256) void att_scale_kernel(float* __restrict__ att)
{
    const int tid = threadIdx.x;
    const int row = blockIdx.x * 8 + (tid >> 5);
    const int lane = tid & 31;
    const int t = row & (Tn - 1);
    const float s = g_Linv[row];
    float4* p4 = (float4*)(att + (size_t)row * Tn);
    const int n4 = (t >> 2) + 1;
    for (int i = lane; i < n4; i += 32) {
        float4 v = p4[i];
        v.x *= s; v.y *= s; v.z *= s; v.w *= s;
        p4[i] = v;
    }
}

// ---------------------------------------------------------------------------
extern "C" void kernel_launch(void* const* d_in, const int* in_sizes, int n_in,
                              void* d_out, int out_size)
{
    const float* x  = (const float*)d_in[0];
    const float* Wq = (const float*)d_in[1];
    const float* bq = (const float*)d_in[2];
    const float* Wk = (const float*)d_in[3];
    const float* bk = (const float*)d_in[4];
    const float* Wv = (const float*)d_in[5];
    const float* bv = (const float*)d_in[6];
    const float* Wo = (const float*)d_in[7];
    const float* bo = (const float*)d_in[8];
    float* out = (float*)d_out;
    float* attOut = out + YSIZE;

    static int configured = 0;
    if (!configured) {
        cudaFuncSetAttribute(qkv_kernel,  cudaFuncAttributeMaxDynamicSharedMemorySize, GEMM2_SMEM);
        cudaFuncSetAttribute(oproj_kernel, cudaFuncAttributeMaxDynamicSharedMemorySize, GEMM2_SMEM);
        cudaFuncSetAttribute(attn_kernel, cudaFuncAttributeMaxDynamicSharedMemorySize, ATTN_SMEM);
        configured = 1;
    }

    split_all_kernel<<<(YSIZE + 4 * Cn * Cn) / 1024, 256>>>(x, Wq, Wk, Wv, Wo);

    qkv_kernel<<<dim3(Cn / 128, BT / 128, 3), 256, GEMM2_SMEM>>>(bq, bk, bv);
    attn_kernel<<<dim3(Tn / 128, Hn, Bn), 512, ATTN_SMEM>>>(attOut);
    att_scale_kernel<<<(Bn * Hn * Tn) / 8, 256>>>(attOut);
    oproj_kernel<<<dim3(Cn / 128, BT / 128), 256, GEMM2_SMEM>>>(bo, out);
}

// round 17
// speedup vs baseline: 1.1512x; 1.0501x over previous
#include <cuda_runtime.h>
#include <cuda_fp16.h>

// Problem constants
#define Bn 2
#define Tn 2048
#define Cn 1024
#define Hn 16
#define Dn 64
#define BT (Bn * Tn)                       // 4096
#define YSIZE (BT * Cn)                    // 4194304
#define QKVSZ (Bn * Hn * Tn * Dn)          // 4194304
#define ATTELEMS ((size_t)Bn * Hn * Tn * Tn)   // 134217728

typedef unsigned short u16;
typedef unsigned int u32;

// f16 plane scratch (device globals -- no allocation allowed)
__device__ u16 g_xFH[YSIZE], g_xFL[YSIZE];   // x f16 hi/lo
__device__ u16 g_WqFH[Cn*Cn];                // weights f16 hi only
__device__ u16 g_WkFH[Cn*Cn];
__device__ u16 g_WvFH[Cn*Cn];
__device__ u16 g_WoFH[Cn*Cn];
__device__ u16 g_Qh[QKVSZ];                  // fp16 [B,H,T,D], PRE-SCALED by 0.125*log2(e)
__device__ u16 g_Kh[QKVSZ];
__device__ u16 g_Vh[QKVSZ];
__device__ u16 g_YFH[YSIZE], g_YFL[YSIZE];   // [B,T,C] f16 hi/lo
__device__ u16 g_E[ATTELEMS];                // unnormalized exp (f16 bits), causal region
__device__ float g_Linv[Bn * Hn * Tn];

// ---------------------------------------------------------------------------
// helpers
// ---------------------------------------------------------------------------
__device__ __forceinline__ u32 sptr(const void* p) {
    return (u32)__cvta_generic_to_shared(p);
}
__device__ __forceinline__ void split1h(float x, u16& h, u16& l) {
    __half hb = __float2half(x);
    h = __half_as_ushort(hb);
    l = __half_as_ushort(__float2half(x - __half2float(hb)));
}
__device__ __forceinline__ void split_store4h(u16* H, u16* L, int idx, float4 v) {
    u16 h[4], l[4];
    split1h(v.x, h[0], l[0]); split1h(v.y, h[1], l[1]);
    split1h(v.z, h[2], l[2]); split1h(v.w, h[3], l[3]);
    *(uint2*)(H + idx) = make_uint2((u32)h[0] | ((u32)h[1] << 16),
                                    (u32)h[2] | ((u32)h[3] << 16));
    *(uint2*)(L + idx) = make_uint2((u32)l[0] | ((u32)l[1] << 16),
                                    (u32)l[2] | ((u32)l[3] << 16));
}
__device__ __forceinline__ void store4h_hi(u16* H, int idx, float4 v) {
    u16 h0 = __half_as_ushort(__float2half(v.x));
    u16 h1 = __half_as_ushort(__float2half(v.y));
    u16 h2 = __half_as_ushort(__float2half(v.z));
    u16 h3 = __half_as_ushort(__float2half(v.w));
    *(uint2*)(H + idx) = make_uint2((u32)h0 | ((u32)h1 << 16),
                                    (u32)h2 | ((u32)h3 << 16));
}
// fp16 mma
__device__ __forceinline__ void mma16h(float c[4], const u32 a[4], u32 b0, u32 b1) {
    asm volatile(
        "mma.sync.aligned.m16n8k16.row.col.f32.f16.f16.f32 "
        "{%0,%1,%2,%3}, {%4,%5,%6,%7}, {%8,%9}, {%0,%1,%2,%3};\n"
        : "+f"(c[0]), "+f"(c[1]), "+f"(c[2]), "+f"(c[3])
        : "r"(a[0]), "r"(a[1]), "r"(a[2]), "r"(a[3]), "r"(b0), "r"(b1));
}
__device__ __forceinline__ void ldsm4(u32 r[4], u32 addr) {
    asm volatile("ldmatrix.sync.aligned.m8n8.x4.shared.b16 {%0,%1,%2,%3}, [%4];"
        : "=r"(r[0]), "=r"(r[1]), "=r"(r[2]), "=r"(r[3]) : "r"(addr));
}
__device__ __forceinline__ void ldsm4t(u32 r[4], u32 addr) {
    asm volatile("ldmatrix.sync.aligned.m8n8.x4.trans.shared.b16 {%0,%1,%2,%3}, [%4];"
        : "=r"(r[0]), "=r"(r[1]), "=r"(r[2]), "=r"(r[3]) : "r"(addr));
}
__device__ __forceinline__ void cpa16(u32 sdst, const void* g) {
    asm volatile("cp.async.cg.shared.global [%0], [%1], 16;\n" :: "r"(sdst), "l"(g));
}
#define CP_COMMIT() asm volatile("cp.async.commit_group;\n")
#define CP_WAIT0()  asm volatile("cp.async.wait_group 0;\n")

// ---------------------------------------------------------------------------
// Fused prep: x -> f16 hi/lo planes; Wq,Wk,Wv,Wo -> f16 hi plane.
// ---------------------------------------------------------------------------
__global__ __launch_bounds__(256) void split_all_kernel(
    const float* __restrict__ x,  const float* __restrict__ wq,
    const float* __restrict__ wk, const float* __restrict__ wv,
    const float* __restrict__ wo)
{
    int i = (blockIdx.x * 256 + threadIdx.x) * 4;
    if (i < YSIZE) {
        split_store4h(g_xFH, g_xFL, i, *(const float4*)(x + i));
    } else {
        int k = i - YSIZE;
        int seg = k >> 20;
        int off = k & ((1 << 20) - 1);
        switch (seg) {
            case 0: store4h_hi(g_WqFH, off, *(const float4*)(wq + off)); break;
            case 1: store4h_hi(g_WkFH, off, *(const float4*)(wk + off)); break;
            case 2: store4h_hi(g_WvFH, off, *(const float4*)(wv + off)); break;
            default: store4h_hi(g_WoFH, off, *(const float4*)(wo + off)); break;
        }
    }
}

// ---------------------------------------------------------------------------
// GEMM mainloop (2-stage): C(128x128) = (Ah+Al) @ Wh^T, f16, 2 mma/step.
// 256 threads = 8 warps (wy 2 x wx 4), warp tile 64x32, k-chunk 32, dbuf.
// smem: [stage 2][plane 3: AH AL WH][128][40] = 61440 bytes, 2 CTAs/SM.
// ---------------------------------------------------------------------------
#define G2STR 40
#define G2PLANE (128 * G2STR)            // 5120 u16
#define G2STAGE (3 * G2PLANE)            // 15360 u16
#define GEMM2_SMEM (2 * G2STAGE * 2)     // 61440 bytes

__device__ __forceinline__ void gemm_mainloop(
    const u16* __restrict__ AH, const u16* __restrict__ AL,
    const u16* __restrict__ WH,
    int m0, int n0, float acc[4][4][4])
{
    extern __shared__ u16 gsm[];
    const int tid = threadIdx.x, lane = tid & 31, w = tid >> 5;
    const int wy = w >> 2, wx = w & 3;
    const u32 sbase = sptr(gsm);
    const u32 aoff = (lane & 15) * (G2STR * 2) + (lane >> 4) * 16;
    const u32 boff = ((lane & 7) + ((lane >> 4) << 3)) * (G2STR * 2) + ((lane >> 3) & 1) * 16;

    const u16* srcs[3] = {AH, AL, WH};
    const int rb3[3] = {m0, m0, n0};

    auto loadbuf = [&](int stg, int kc) {
        #pragma unroll
        for (int p = 0; p < 3; p++) {
            const u16* sp = srcs[p];
            #pragma unroll
            for (int j = 0; j < 2; j++) {
                int c = tid + 256 * j;
                int r = c >> 2, c16 = c & 3;
                u32 d = sbase + (stg * G2STAGE + p * G2PLANE + r * G2STR + c16 * 8) * 2;
                cpa16(d, sp + (size_t)(rb3[p] + r) * Cn + kc * 32 + c16 * 8);
            }
        }
    };

    loadbuf(0, 0); CP_COMMIT(); CP_WAIT0();
    __syncthreads();

    const int NC = Cn / 32;   // 32
    for (int kc = 0; kc < NC; kc++) {
        const int buf = kc & 1;
        if (kc + 1 < NC) { loadbuf(buf ^ 1, kc + 1); CP_COMMIT(); }

        const u32 ab  = sbase + (buf * G2STAGE + 0 * G2PLANE) * 2;
        const u32 alb = sbase + (buf * G2STAGE + 1 * G2PLANE) * 2;
        const u32 wb  = sbase + (buf * G2STAGE + 2 * G2PLANE) * 2;

        #pragma unroll
        for (int s = 0; s < 2; s++) {
            const u32 kb = s * 32;
            u32 ah[4][4], al[4][4];
            #pragma unroll
            for (int mt = 0; mt < 4; mt++) {
                const u32 rb = (wy * 64 + mt * 16) * (G2STR * 2) + kb + aoff;
                ldsm4(ah[mt], ab + rb);
                ldsm4(al[mt], alb + rb);
            }
            u32 bh[2][4];
            #pragma unroll
            for (int p = 0; p < 2; p++)
                ldsm4(bh[p], wb + (wx * 32 + p * 16) * (G2STR * 2) + kb + boff);
            #pragma unroll
            for (int nt = 0; nt < 4; nt++) {
                const u32 b0 = bh[nt >> 1][(nt & 1) * 2], b1 = bh[nt >> 1][(nt & 1) * 2 + 1];
                #pragma unroll
                for (int mt = 0; mt < 4; mt++) {
                    mma16h(acc[mt][nt], ah[mt], b0, b1);
                    mma16h(acc[mt][nt], al[mt], b0, b1);
                }
            }
        }
        if (kc + 1 < NC) { CP_WAIT0(); __syncthreads(); }
    }
}

// ---------------------------------------------------------------------------
// Fused QKV projection. Outputs single fp16 plane [B,H,T,D].
// Q is PRE-SCALED by 0.125*log2(e) so S = Q K^T is directly the exp2 argument.
// ---------------------------------------------------------------------------
__global__ __launch_bounds__(256, 2) void qkv_kernel(
    const float* __restrict__ bq, const float* __restrict__ bk,
    const float* __restrict__ bv)
{
    const int mode = blockIdx.z;
    const float* bias = mode == 0 ? bq : (mode == 1 ? bk : bv);
    const u16* W = mode == 0 ? g_WqFH : (mode == 1 ? g_WkFH : g_WvFH);
    u16* dst = mode == 0 ? g_Qh : (mode == 1 ? g_Kh : g_Vh);
    const float osc = (mode == 0) ? 0.18033688f : 1.0f;   // 0.125 * log2(e)

    const int m0 = blockIdx.y * 128, n0 = blockIdx.x * 128;
    float acc[4][4][4] = {};
    gemm_mainloop(g_xFH, g_xFL, W, m0, n0, acc);

    const int tid = threadIdx.x;
    const int w = tid >> 5, lane = tid & 31;
    const int wy = w >> 2, wx = w & 3;
    const int grp = lane >> 2, tig = lane & 3;

    #pragma unroll
    for (int mt = 0; mt < 4; mt++) {
        #pragma unroll
        for (int half = 0; half < 2; half++) {
            const int m = m0 + wy * 64 + mt * 16 + grp + 8 * half;
            const int b = m >> 11;
            const int t = m & (Tn - 1);
            #pragma unroll
            for (int nt = 0; nt < 4; nt++) {
                const int n = n0 + wx * 32 + nt * 8 + 2 * tig;
                const int h = n >> 6, d = n & 63;
                float e0 = (acc[mt][nt][half * 2 + 0] + bias[n]) * osc;
                float e1 = (acc[mt][nt][half * 2 + 1] + bias[n + 1]) * osc;
                u16 q0 = __half_as_ushort(__float2half(e0));
                u16 q1 = __half_as_ushort(__float2half(e1));
                const size_t idx = ((size_t)(b * Hn + h) * Tn + t) * Dn + d;
                *(u32*)&dst[idx] = (u32)q0 | ((u32)q1 << 16);
            }
        }
    }
}

// ---------------------------------------------------------------------------
// Output projection: out = (Yh+Yl) @ WoH^T + bo.
// ---------------------------------------------------------------------------
__global__ __launch_bounds__(256, 2) void oproj_kernel(
    const float* __restrict__ bo, float* __restrict__ out)
{
    const int m0 = blockIdx.y * 128, n0 = blockIdx.x * 128;
    float acc[4][4][4] = {};
    gemm_mainloop(g_YFH, g_YFL, g_WoFH, m0, n0, acc);

    const int tid = threadIdx.x;
    const int w = tid >> 5, lane = tid & 31;
    const int wy = w >> 2, wx = w & 3;
    const int grp = lane >> 2, tig = lane & 3;

    #pragma unroll
    for (int mt = 0; mt < 4; mt++) {
        #pragma unroll
        for (int half = 0; half < 2; half++) {
            const int m = m0 + wy * 64 + mt * 16 + grp + 8 * half;
            #pragma unroll
            for (int nt = 0; nt < 4; nt++) {
                const int n = n0 + wx * 32 + nt * 8 + 2 * tig;
                float2 o = make_float2(acc[mt][nt][half * 2 + 0] + bo[n],
                                       acc[mt][nt][half * 2 + 1] + bo[n + 1]);
                *(float2*)&out[(size_t)m * Cn + n] = o;
            }
        }
    }
}

// ---------------------------------------------------------------------------
// Causal attention. S in log2 domain; e = 2^S via h2exp2 (1 MUFU / 2 elems).
// e stored as f16 bits to g_E (half the bytes of f32); P plane gets same bits.
// Diagonal tile applies mask; upper att region zeroed here (f32).
// smem u16: Q[128][72] | K[128][72] | V[2buf][128][72] | PH[128][136] | rowsum
// ---------------------------------------------------------------------------
#define GSTR 72
#define GS (128 * GSTR)
#define PSTR 136
#define PS (128 * PSTR)
#define AQ  0
#define AK  GS
#define AVB (2 * GS)                 // 2 bufs: 2GS..4GS
#define APH (4 * GS)                 // 36864
#define ARS (APH + PS)               // 54272
#define ATTN_SMEM (ARS * 2 + 512)    // 109056 bytes

__global__ __launch_bounds__(512) void attn_kernel(float* __restrict__ att)
{
    extern __shared__ u16 smu[];
    float* rowsum = (float*)(smu + ARS);

    const u32 sbase = sptr(smu);
    const u32 sQ  = sbase;
    const u32 sK  = sbase + AK * 2;
    const u32 sPH = sbase + APH * 2;

    const int tid = threadIdx.x;
    const int w = tid >> 5, lane = tid & 31;
    const int wy = w >> 2, wx = w & 3;
    const int grp = lane >> 2, tig = lane & 3;

    const int qt = gridDim.x - 1 - blockIdx.x;
    const int h = blockIdx.y, b = blockIdx.z;
    const int bh = b * Hn + h;
    const int q0 = qt * 128;
    const size_t qb = (size_t)bh * Tn * Dn;
    float* attp = att + (size_t)bh * Tn * Tn + (size_t)q0 * Tn;
    u16* gEp = g_E + (size_t)bh * Tn * Tn + (size_t)q0 * Tn;

    const u32 aoff = (lane & 15) * (GSTR * 2) + (lane >> 4) * 16;
    const u32 boff = ((lane & 7) + ((lane >> 4) << 3)) * (GSTR * 2) + ((lane >> 3) & 1) * 16;
    const u32 poff = (lane & 15) * (PSTR * 2) + (lane >> 4) * 16;

    auto loadQ = [&]() {
        #pragma unroll
        for (int j = 0; j < 2; j++) {
            int c = tid + 512 * j;
            int r = c >> 3, col = (c & 7) * 8;
            cpa16(sbase + (AQ + r * GSTR + col) * 2, g_Qh + qb + (size_t)(q0 + r) * Dn + col);
        }
    };
    auto loadK = [&](int kt) {
        #pragma unroll
        for (int j = 0; j < 2; j++) {
            int c = tid + 512 * j;
            int r = c >> 3, col = (c & 7) * 8;
            cpa16(sbase + (AK + r * GSTR + col) * 2, g_Kh + qb + (size_t)(kt * 128 + r) * Dn + col);
        }
    };
    auto loadV = [&](int kt, int vb) {
        #pragma unroll
        for (int j = 0; j < 2; j++) {
            int c = tid + 512 * j;
            int r = c >> 3, col = (c & 7) * 8;
            cpa16(sbase + ((AVB + vb * GS) + r * GSTR + col) * 2,
                  g_Vh + qb + (size_t)(kt * 128 + r) * Dn + col);
        }
    };

    if (tid < 128) rowsum[tid] = 0.f;
    loadQ();
    loadK(0);
    loadV(0, 0);
    CP_COMMIT();
    CP_WAIT0();
    __syncthreads();

    float accy[2][2][4] = {};
    float lpart[2][2] = {};
    const int qbl = wy * 32;

    for (int kt = 0; kt <= qt; kt++) {
        const int k0 = kt * 128;
        const int vb = kt & 1;
        const int ktn = (kt + 1 <= qt) ? kt + 1 : qt;

        loadV(ktn, vb ^ 1);
        CP_COMMIT();

        // ---- S = Q K^T (fp16 x1), result in log2 domain ----
        float sfrag[2][4][4] = {};
        #pragma unroll
        for (int ds = 0; ds < 4; ds++) {
            const u32 kb = ds * 32;
            u32 ah[2][4];
            #pragma unroll
            for (int mt = 0; mt < 2; mt++)
                ldsm4(ah[mt], sQ + (qbl + mt * 16) * (GSTR * 2) + kb + aoff);
            u32 kh[2][4];
            #pragma unroll
            for (int p = 0; p < 2; p++)
                ldsm4(kh[p], sK + (wx * 32 + p * 16) * (GSTR * 2) + kb + boff);
            #pragma unroll
            for (int nt = 0; nt < 4; nt++) {
                const u32 b0 = kh[nt >> 1][(nt & 1) * 2], b1 = kh[nt >> 1][(nt & 1) * 2 + 1];
                #pragma unroll
                for (int mt = 0; mt < 2; mt++)
                    mma16h(sfrag[mt][nt], ah[mt], b0, b1);
            }
        }

        // ---- e = 2^S via f16x2 MUFU; store f16 bits to g_E + P plane ----
        if (kt < qt) {
            #pragma unroll
            for (int mt = 0; mt < 2; mt++) {
                #pragma unroll
                for (int half = 0; half < 2; half++) {
                    const int ql = qbl + mt * 16 + grp + 8 * half;
                    #pragma unroll
                    for (int nt = 0; nt < 4; nt++) {
                        const int klc = wx * 32 + nt * 8 + 2 * tig;
                        __half2 hs = __floats2half2_rn(sfrag[mt][nt][half * 2 + 0],
                                                       sfrag[mt][nt][half * 2 + 1]);
                        __half2 he = h2exp2(hs);
                        float2 ef = __half22float2(he);
                        lpart[mt][half] += ef.x + ef.y;
                        *(u32*)(gEp + (size_t)ql * Tn + k0 + klc) = *(u32*)&he;
                        *(u32*)&smu[APH + ql * PSTR + klc] = *(u32*)&he;
                    }
                }
            }
        } else {
            // diagonal tile: apply causal mask
            #pragma unroll
            for (int mt = 0; mt < 2; mt++) {
                #pragma unroll
                for (int half = 0; half < 2; half++) {
                    const int ql = qbl + mt * 16 + grp + 8 * half;
                    const int qg = q0 + ql;
                    #pragma unroll
                    for (int nt = 0; nt < 4; nt++) {
                        const int klc = wx * 32 + nt * 8 + 2 * tig;
                        __half2 hs = __floats2half2_rn(sfrag[mt][nt][half * 2 + 0],
                                                       sfrag[mt][nt][half * 2 + 1]);
                        __half2 he = h2exp2(hs);
                        float2 ef = __half22float2(he);
                        if (k0 + klc     > qg) ef.x = 0.f;
                        if (k0 + klc + 1 > qg) ef.y = 0.f;
                        __half2 hm = __floats2half2_rn(ef.x, ef.y);
                        lpart[mt][half] += ef.x + ef.y;
                        *(u32*)(gEp + (size_t)ql * Tn + k0 + klc) = *(u32*)&hm;
                        *(u32*)&smu[APH + ql * PSTR + klc] = *(u32*)&hm;
                    }
                }
            }
        }
        __syncthreads();

        loadK(ktn);
        CP_COMMIT();

        // ---- y += P V (f16 x1), V via ldmatrix.trans ----
        const u32 sV = sbase + (AVB + vb * GS) * 2;
        #pragma unroll
        for (int ks = 0; ks < 8; ks++) {
            u32 ph[2][4];
            #pragma unroll
            for (int mt = 0; mt < 2; mt++)
                ldsm4(ph[mt], sPH + (qbl + mt * 16) * (PSTR * 2) + ks * 32 + poff);
            u32 vh[4];
            ldsm4t(vh, sV + (ks * 16) * (GSTR * 2) + wx * 32 + aoff);
            #pragma unroll
            for (int ntv = 0; ntv < 2; ntv++) {
                const u32 b0 = vh[2 * ntv], b1 = vh[2 * ntv + 1];
                #pragma unroll
                for (int mt = 0; mt < 2; mt++)
                    mma16h(accy[mt][ntv], ph[mt], b0, b1);
            }
        }

        CP_WAIT0();
        __syncthreads();
    }

    #pragma unroll
    for (int mt = 0; mt < 2; mt++) {
        #pragma unroll
        for (int half = 0; half < 2; half++) {
            float v = lpart[mt][half];
            v += __shfl_xor_sync(0xffffffffu, v, 1);
            v += __shfl_xor_sync(0xffffffffu, v, 2);
            if (tig == 0) atomicAdd(&rowsum[qbl + mt * 16 + grp + 8 * half], v);
        }
    }
    __syncthreads();
    if (tid < 128) g_Linv[(size_t)bh * Tn + q0 + tid] = 1.0f / rowsum[tid];

    // ---- write y (normalized) as f16 hi/lo planes ----
    #pragma unroll
    for (int mt = 0; mt < 2; mt++) {
        #pragma unroll
        for (int half = 0; half < 2; half++) {
            const int ql = qbl + mt * 16 + grp + 8 * half;
            const float li = 1.0f / rowsum[ql];
            const int tg = q0 + ql;
            #pragma unroll
            for (int ntv = 0; ntv < 2; ntv++) {
                const int d = wx * 16 + ntv * 8 + 2 * tig;
                float y0 = accy[mt][ntv][half * 2 + 0] * li;
                float y1 = accy[mt][ntv][half * 2 + 1] * li;
                u16 h0, l0, h1, l1;
                split1h(y0, h0, l0); split1h(y1, h1, l1);
                const size_t idx = (size_t)(b * Tn + tg) * Cn + h * Dn + d;
                *(u32*)&g_YFH[idx] = (u32)h0 | ((u32)h1 << 16);
                *(u32*)&g_YFL[idx] = (u32)l0 | ((u32)l1 << 16);
            }
        }
    }

    // ---- zero strictly-upper att region (f32 output) ----
    const int zc0 = (qt + 1) * 128;
    if (zc0 < Tn) {
        const int nz4 = (Tn - zc0) >> 2;
        for (int idx = tid; idx < 128 * nz4; idx += 512) {
            int r = idx / nz4, c = (idx - r * nz4) * 4;
            *(float4*)(attp + (size_t)r * Tn + zc0 + c) = make_float4(0.f, 0.f, 0.f, 0.f);
        }
    }
}

// ---------------------------------------------------------------------------
// Normalize att: read f16 e from g_E, scale by 1/l, write f32 causal region
// (each row up to its 128-tile boundary; masked in-tile positions are exact 0).
// One warp per row, uint4 (8-elem) granularity.
// ---------------------------------------------------------------------------
__global__ __launch_bounds__(256) void att_scale_kernel(float* __restrict__ att)
{
    const int tid = threadIdx.x;
    const int row = blockIdx.x * 8 + (tid >> 5);
    const int lane = tid & 31;
    const int t = row & (Tn - 1);
    const float s = g_Linv[row];
    const uint4* e4 = (const uint4*)(g_E + (size_t)row * Tn);
    float4* p4 = (float4*)(att + (size_t)row * Tn);
    const int nb = ((t >> 7) + 1) * 16;   // uint4 blocks covering the causal tiles
    for (int i = lane; i < nb; i += 32) {
        uint4 ev = e4[i];
        __half2 h0 = *(__half2*)&ev.x, h1 = *(__half2*)&ev.y;
        __half2 h2 = *(__half2*)&ev.z, h3 = *(__half2*)&ev.w;
        float2 f0 = __half22float2(h0), f1 = __half22float2(h1);
        float2 f2 = __half22float2(h2), f3 = __half22float2(h3);
        p4[2 * i]     = make_float4(f0.x * s, f0.y * s, f1.x * s, f1.y * s);
        p4[2 * i + 1] = make_float4(f2.x * s, f2.y * s, f3.x * s, f3.y * s);
    }
}

// ---------------------------------------------------------------------------
extern "C" void kernel_launch(void* const* d_in, const int* in_sizes, int n_in,
                              void* d_out, int out_size)
{
    const float* x  = (const float*)d_in[0];
    const float* Wq = (const float*)d_in[1];
    const float* bq = (const float*)d_in[2];
    const float* Wk = (const float*)d_in[3];
    const float* bk = (const float*)d_in[4];
    const float* Wv = (const float*)d_in[5];
    const float* bv = (const float*)d_in[6];
    const float* Wo = (const float*)d_in[7];
    const float* bo = (const float*)d_in[8];
    float* out = (float*)d_out;
    float* attOut = out + YSIZE;

    static int configured = 0;
    if (!configured) {
        cudaFuncSetAttribute(qkv_kernel,  cudaFuncAttributeMaxDynamicSharedMemorySize, GEMM2_SMEM);
        cudaFuncSetAttribute(oproj_kernel, cudaFuncAttributeMaxDynamicSharedMemorySize, GEMM2_SMEM);
        cudaFuncSetAttribute(attn_kernel, cudaFuncAttributeMaxDynamicSharedMemorySize, ATTN_SMEM);
        configured = 1;
    }

    split_all_kernel<<<(YSIZE + 4 * Cn * Cn) / 1024, 256>>>(x, Wq, Wk, Wv, Wo);

    qkv_kernel<<<dim3(Cn / 128, BT / 128, 3), 256, GEMM2_SMEM>>>(bq, bk, bv);
    attn_kernel<<<dim3(Tn / 128, Hn, Bn), 512, ATTN_SMEM>>>(attOut);
    att_scale_kernel<<<(Bn * Hn * Tn) / 8, 256>>>(attOut);
    oproj_kernel<<<dim3(Cn / 128, BT / 128), 256, GEMM2_SMEM>>>(bo, out);
}